// round 1
// baseline (speedup 1.0000x reference)
#include <cuda_runtime.h>
#include <cuda_bf16.h>

// Problem constants (match reference_code)
#define PQ    400      // num queries
#define PP    200000   // num points
#define NB    100      // num instances
#define NCHUNK 8       // p-chunks per q row

// Scratch (device globals; no allocations allowed)
__device__ unsigned char d_lab8[PP];
__device__ float d_G[PQ * NB];     // binned (f1 - f0)
__device__ float d_Pb[PQ * NB];    // binned sigmoid
__device__ float d_Sel[PQ];        // sum of sel (f0 = 0.75*sel)
__device__ int   d_cnt[NB];        // points per instance

// ---------------------------------------------------------------------------
// Zero accumulators
// ---------------------------------------------------------------------------
__global__ void zero_kernel() {
    int i = blockIdx.x * blockDim.x + threadIdx.x;
    if (i < PQ * NB) { d_G[i] = 0.f; d_Pb[i] = 0.f; }
    if (i < PQ) d_Sel[i] = 0.f;
    if (i < NB) d_cnt[i] = 0;
}

// ---------------------------------------------------------------------------
// Prep: labels int32 -> uint8, histogram counts
// ---------------------------------------------------------------------------
__global__ void prep_kernel(const int* __restrict__ labels) {
    __shared__ int h[NB];
    if (threadIdx.x < NB) h[threadIdx.x] = 0;
    __syncthreads();

    int i = blockIdx.x * blockDim.x + threadIdx.x;   // index in groups of 4
    if (i < PP / 4) {
        int4 l4 = reinterpret_cast<const int4*>(labels)[i];
        uchar4 u;
        u.x = (unsigned char)l4.x; u.y = (unsigned char)l4.y;
        u.z = (unsigned char)l4.z; u.w = (unsigned char)l4.w;
        reinterpret_cast<uchar4*>(d_lab8)[i] = u;
        atomicAdd(&h[l4.x], 1);
        atomicAdd(&h[l4.y], 1);
        atomicAdd(&h[l4.z], 1);
        atomicAdd(&h[l4.w], 1);
    }
    __syncthreads();
    if (threadIdx.x < NB && h[threadIdx.x] != 0)
        atomicAdd(&d_cnt[threadIdx.x], h[threadIdx.x]);
}

// ---------------------------------------------------------------------------
// Main element-wise + binning kernel
//   e  = exp(-|x|), s = 1/(1+e), L = log1p(e) (poly), os = e*s
//   A  = os^2 * L,  B = s^2 * (|x| + L)
//   x>=0: f1=.25A f0=.75B p=s   |  x<0: f1=.25B f0=.75A p=os
//   sel = (x<0 ? A : B);  f1-f0 = 0.25*(A+B) - sel;  f0 = 0.75*sel
// ---------------------------------------------------------------------------
__device__ __forceinline__ float elem_process(float x, int lab,
                                              float* __restrict__ binG,
                                              float* __restrict__ binP) {
    float ax = fabsf(x);
    float e  = __expf(-ax);                 // EX2 (MUFU) + FMUL
    float s;
    asm("rcp.approx.ftz.f32 %0, %1;" : "=f"(s) : "f"(e + 1.0f));  // MUFU.RCP

    // log1p(e) on e in (0,1]:  L = ln(3/2) + ln(1 + u/3), u = 2e-1 (deg 7)
    float u = fmaf(2.0f, e, -1.0f);
    float L;
    L = fmaf(6.5321048e-5f,  u, -2.2862368e-4f);
    L = fmaf(L, u,  8.2304527e-4f);
    L = fmaf(L, u, -3.0864198e-3f);
    L = fmaf(L, u,  1.2345679e-2f);
    L = fmaf(L, u, -5.5555556e-2f);
    L = fmaf(L, u,  3.3333333e-1f);
    L = fmaf(L, u,  4.0546511e-1f);

    float os  = e * s;
    float axL = ax + L;
    float A   = (os * os) * L;
    float B   = (s * s) * axL;

    bool neg  = (x < 0.0f);
    float sel = neg ? A : B;
    float pp  = neg ? os : s;
    float g   = fmaf(A + B, 0.25f, -sel);

    atomicAdd(binG + lab, g);
    atomicAdd(binP + lab, pp);
    return sel;
}

__global__ __launch_bounds__(256) void cost_kernel(const float* __restrict__ pm) {
    // [replica][G/P][bins+pad]
    __shared__ float bins[2][2][NB + 4];
    int tid = threadIdx.x;
    for (int i = tid; i < 2 * 2 * (NB + 4); i += 256)
        (&bins[0][0][0])[i] = 0.f;
    __syncthreads();

    int q     = blockIdx.x;
    int chunk = blockIdx.y;

    const int nf4    = PP / 4;               // 50000 float4 per row
    const int f4_per = nf4 / NCHUNK;         // 6250
    int s4 = chunk * f4_per;
    int e4 = s4 + f4_per;

    const float4* xv = reinterpret_cast<const float4*>(pm + (size_t)q * PP);
    const uchar4* lv = reinterpret_cast<const uchar4*>(d_lab8);

    int rep = tid & 1;
    float* binG = &bins[rep][0][0];
    float* binP = &bins[rep][1][0];

    float selacc = 0.f;
    for (int i4 = s4 + tid; i4 < e4; i4 += 256) {
        float4 xs = __ldcs(&xv[i4]);    // streaming: no reuse of pred_masks
        uchar4 lb = lv[i4];
        selacc += elem_process(xs.x, lb.x, binG, binP);
        selacc += elem_process(xs.y, lb.y, binG, binP);
        selacc += elem_process(xs.z, lb.z, binG, binP);
        selacc += elem_process(xs.w, lb.w, binG, binP);
    }
    __syncthreads();

    if (tid < NB) {
        float gs = bins[0][0][tid] + bins[1][0][tid];
        float ps = bins[0][1][tid] + bins[1][1][tid];
        atomicAdd(&d_G[q * NB + tid], gs);
        atomicAdd(&d_Pb[q * NB + tid], ps);
    }
    // warp-reduce selacc, one global atomic per warp
    #pragma unroll
    for (int o = 16; o; o >>= 1)
        selacc += __shfl_xor_sync(0xFFFFFFFFu, selacc, o);
    if ((tid & 31) == 0)
        atomicAdd(&d_Sel[q], selacc);
}

// ---------------------------------------------------------------------------
// Finalize: out[q,j] = cost_mask + cost_dice
// ---------------------------------------------------------------------------
__global__ void finalize_kernel(float* __restrict__ out) {
    int q = blockIdx.x, tid = threadIdx.x;
    __shared__ float red[4];

    float pv = (tid < NB) ? d_Pb[q * NB + tid] : 0.f;
    float w = pv;
    #pragma unroll
    for (int o = 16; o; o >>= 1)
        w += __shfl_xor_sync(0xFFFFFFFFu, w, o);
    if ((tid & 31) == 0) red[tid >> 5] = w;
    __syncthreads();
    float Psum = red[0] + red[1] + red[2] + red[3];

    if (tid < NB) {
        float cm  = (d_G[q * NB + tid] + 0.75f * d_Sel[q]) * (1.0f / (float)PP);
        float num = fmaf(2.0f, pv, 1.0f);
        float den = Psum + (float)d_cnt[tid] + 1.0f;
        out[q * NB + tid] = cm + 1.0f - num / den;
    }
}

// ---------------------------------------------------------------------------
extern "C" void kernel_launch(void* const* d_in, const int* in_sizes, int n_in,
                              void* d_out, int out_size) {
    const float* pm     = (const float*)d_in[0];
    const int*   labels = (const int*)d_in[1];
    (void)in_sizes; (void)n_in; (void)out_size;

    zero_kernel<<<160, 256>>>();
    prep_kernel<<<(PP / 4 + 255) / 256, 256>>>(labels);
    cost_kernel<<<dim3(PQ, NCHUNK), 256>>>(pm);
    finalize_kernel<<<PQ, 128>>>((float*)d_out);
}

// round 2
// speedup vs baseline: 1.2137x; 1.2137x over previous
#include <cuda_runtime.h>
#include <cuda_bf16.h>

// Problem constants (match reference_code)
#define PQ    400      // num queries
#define PP    200000   // num points
#define NB    100      // num instances
#define NCHUNK 8       // p-chunks per q row
#define NREP  4        // smem bin replicas

// Fixed-point packing: hi 32 bits = g (signed, scale 2^13), lo 32 = p (unsigned, scale 2^17)
#define MAGICF    12582912.0f      // 1.5 * 2^23
#define MAGIC_I   0x4B400000u
#define SCALE_G   8192.0f          // 2^13
#define SCALE_P   131072.0f        // 2^17
#define INV_SCALE_G (1.0f / 8192.0f)
#define INV_SCALE_P (1.0f / 131072.0f)

// Scratch (device globals; no allocations allowed)
__device__ unsigned char d_lab8[PP];
__device__ float d_G[PQ * NB];     // binned (f1 - f0)
__device__ float d_Pb[PQ * NB];    // binned sigmoid
__device__ float d_Sel[PQ];        // sum of sel (f0 = 0.75*sel)
__device__ int   d_cnt[NB];        // points per instance

// ---------------------------------------------------------------------------
// Zero accumulators
// ---------------------------------------------------------------------------
__global__ void zero_kernel() {
    int i = blockIdx.x * blockDim.x + threadIdx.x;
    if (i < PQ * NB) { d_G[i] = 0.f; d_Pb[i] = 0.f; }
    if (i < PQ) d_Sel[i] = 0.f;
    if (i < NB) d_cnt[i] = 0;
}

// ---------------------------------------------------------------------------
// Prep: labels int32 -> uint8, histogram counts
// ---------------------------------------------------------------------------
__global__ void prep_kernel(const int* __restrict__ labels) {
    __shared__ int h[NB];
    if (threadIdx.x < NB) h[threadIdx.x] = 0;
    __syncthreads();

    int i = blockIdx.x * blockDim.x + threadIdx.x;   // index in groups of 4
    if (i < PP / 4) {
        int4 l4 = reinterpret_cast<const int4*>(labels)[i];
        uchar4 u;
        u.x = (unsigned char)l4.x; u.y = (unsigned char)l4.y;
        u.z = (unsigned char)l4.z; u.w = (unsigned char)l4.w;
        reinterpret_cast<uchar4*>(d_lab8)[i] = u;
        atomicAdd(&h[l4.x], 1);
        atomicAdd(&h[l4.y], 1);
        atomicAdd(&h[l4.z], 1);
        atomicAdd(&h[l4.w], 1);
    }
    __syncthreads();
    if (threadIdx.x < NB && h[threadIdx.x] != 0)
        atomicAdd(&d_cnt[threadIdx.x], h[threadIdx.x]);
}

// ---------------------------------------------------------------------------
// Main element-wise + binning kernel
//   e  = exp(-|x|), s = 1/(1+e), L = log1p(e) (poly), os = e*s
//   A  = os^2 * L,  B = s^2 * (|x| + L)
//   x>=0: f1=.25A f0=.75B p=s   |  x<0: f1=.25B f0=.75A p=os
//   sel = (x<0 ? A : B);  f1-f0 = 0.25*(A+B) - sel;  f0 = 0.75*sel
//   g and p are packed fixed-point into ONE u64 smem atomic per element.
// ---------------------------------------------------------------------------
__device__ __forceinline__ float elem_process(float x, int lab,
                                              unsigned long long* __restrict__ bin) {
    float ax = fabsf(x);
    float e  = __expf(-ax);                 // EX2 (MUFU) + FMUL
    float s;
    asm("rcp.approx.ftz.f32 %0, %1;" : "=f"(s) : "f"(e + 1.0f));  // MUFU.RCP

    // log1p(e) on e in (0,1]:  L = ln(3/2) + ln(1 + u/3), u = 2e-1 (deg 7)
    float u = fmaf(2.0f, e, -1.0f);
    float L;
    L = fmaf(6.5321048e-5f,  u, -2.2862368e-4f);
    L = fmaf(L, u,  8.2304527e-4f);
    L = fmaf(L, u, -3.0864198e-3f);
    L = fmaf(L, u,  1.2345679e-2f);
    L = fmaf(L, u, -5.5555556e-2f);
    L = fmaf(L, u,  3.3333333e-1f);
    L = fmaf(L, u,  4.0546511e-1f);

    float os  = e * s;
    float axL = ax + L;
    float A   = (os * os) * L;
    float B   = (s * s) * axL;

    bool neg  = (x < 0.0f);
    float sel = neg ? A : B;
    float pp  = neg ? os : s;
    float g   = fmaf(A + B, 0.25f, -sel);

    // Fixed-point via magic number (no F2I): round-to-nearest into mantissa
    unsigned int gi = __float_as_uint(fmaf(g,  SCALE_G, MAGICF)) - MAGIC_I; // signed in u32
    unsigned int pi = __float_as_uint(fmaf(pp, SCALE_P, MAGICF)) - MAGIC_I; // nonneg

    unsigned long long pk = ((unsigned long long)gi << 32) | (unsigned long long)pi;
    atomicAdd(bin + lab, pk);
    return sel;
}

__global__ __launch_bounds__(256) void cost_kernel(const float* __restrict__ pm) {
    __shared__ unsigned long long bins[NREP][NB + 4];
    int tid = threadIdx.x;
    for (int i = tid; i < NREP * (NB + 4); i += 256)
        (&bins[0][0])[i] = 0ull;
    __syncthreads();

    int q     = blockIdx.x;
    int chunk = blockIdx.y;

    const int nf4    = PP / 4;               // 50000 float4 per row
    const int f4_per = nf4 / NCHUNK;         // 6250
    int s4 = chunk * f4_per;
    int e4 = s4 + f4_per;

    const float4* xv = reinterpret_cast<const float4*>(pm + (size_t)q * PP);
    const uchar4* lv = reinterpret_cast<const uchar4*>(d_lab8);

    unsigned long long* bin = &bins[tid & (NREP - 1)][0];

    float selacc = 0.f;
    for (int i4 = s4 + tid; i4 < e4; i4 += 256) {
        float4 xs = __ldcs(&xv[i4]);    // streaming: no reuse of pred_masks
        uchar4 lb = lv[i4];
        selacc += elem_process(xs.x, lb.x, bin);
        selacc += elem_process(xs.y, lb.y, bin);
        selacc += elem_process(xs.z, lb.z, bin);
        selacc += elem_process(xs.w, lb.w, bin);
    }
    __syncthreads();

    if (tid < NB) {
        unsigned long long v = bins[0][tid] + bins[1][tid]
                             + bins[2][tid] + bins[3][tid];
        int   gi = (int)(v >> 32);                 // carries from lo can't occur (lo bounded)
        unsigned int pi = (unsigned int)(v & 0xFFFFFFFFull);
        atomicAdd(&d_G[q * NB + tid],  (float)gi * INV_SCALE_G);
        atomicAdd(&d_Pb[q * NB + tid], (float)pi * INV_SCALE_P);
    }
    // warp-reduce selacc, one global atomic per warp
    #pragma unroll
    for (int o = 16; o; o >>= 1)
        selacc += __shfl_xor_sync(0xFFFFFFFFu, selacc, o);
    if ((tid & 31) == 0)
        atomicAdd(&d_Sel[q], selacc);
}

// ---------------------------------------------------------------------------
// Finalize: out[q,j] = cost_mask + cost_dice
// ---------------------------------------------------------------------------
__global__ void finalize_kernel(float* __restrict__ out) {
    int q = blockIdx.x, tid = threadIdx.x;
    __shared__ float red[4];

    float pv = (tid < NB) ? d_Pb[q * NB + tid] : 0.f;
    float w = pv;
    #pragma unroll
    for (int o = 16; o; o >>= 1)
        w += __shfl_xor_sync(0xFFFFFFFFu, w, o);
    if ((tid & 31) == 0) red[tid >> 5] = w;
    __syncthreads();
    float Psum = red[0] + red[1] + red[2] + red[3];

    if (tid < NB) {
        float cm  = (d_G[q * NB + tid] + 0.75f * d_Sel[q]) * (1.0f / (float)PP);
        float num = fmaf(2.0f, pv, 1.0f);
        float den = Psum + (float)d_cnt[tid] + 1.0f;
        out[q * NB + tid] = cm + 1.0f - num / den;
    }
}

// ---------------------------------------------------------------------------
extern "C" void kernel_launch(void* const* d_in, const int* in_sizes, int n_in,
                              void* d_out, int out_size) {
    const float* pm     = (const float*)d_in[0];
    const int*   labels = (const int*)d_in[1];
    (void)in_sizes; (void)n_in; (void)out_size;

    zero_kernel<<<160, 256>>>();
    prep_kernel<<<(PP / 4 + 255) / 256, 256>>>(labels);
    cost_kernel<<<dim3(PQ, NCHUNK), 256>>>(pm);
    finalize_kernel<<<PQ, 128>>>((float*)d_out);
}

// round 3
// speedup vs baseline: 1.2779x; 1.0529x over previous
#include <cuda_runtime.h>
#include <cuda_bf16.h>

// Problem constants (match reference_code)
#define PQ    400      // num queries
#define PP    200000   // num points
#define NB    100      // num instances
#define NCHUNK 8       // p-chunks per q row
#define NREP  8        // smem bin replicas

// Fixed-point packing: hi 32 bits = g (signed, scale 2^13), lo 32 = p (unsigned, scale 2^17)
#define MAGICF    12582912.0f      // 1.5 * 2^23
#define MAGIC_I   0x4B400000u
#define SCALE_G   8192.0f          // 2^13
#define SCALE_P   131072.0f       // 2^17
#define INV_SCALE_G (1.0f / 8192.0f)
#define INV_SCALE_P (1.0f / 131072.0f)

// Scratch (device globals; no allocations allowed)
__device__ unsigned char d_lab8[PP];
__device__ float d_G[PQ * NB];     // binned (f1 - f0)
__device__ float d_Pb[PQ * NB];    // binned sigmoid
__device__ float d_Sel[PQ];        // sum of sel (f0 = 0.75*sel)
__device__ int   d_cnt[NB];        // points per instance

// ---------------------------------------------------------------------------
// Packed f32x2 helpers (Blackwell FFMA2 path — PTX only)
// ---------------------------------------------------------------------------
typedef unsigned long long u64;

#define FMA2(d, a, b, c) asm("fma.rn.f32x2 %0, %1, %2, %3;" : "=l"(d) : "l"(a), "l"(b), "l"(c))
#define MUL2(d, a, b)    asm("mul.rn.f32x2 %0, %1, %2;"     : "=l"(d) : "l"(a), "l"(b))
#define ADD2(d, a, b)    asm("add.rn.f32x2 %0, %1, %2;"     : "=l"(d) : "l"(a), "l"(b))

__device__ __forceinline__ u64 pk2(float lo, float hi) {
    u64 r; asm("mov.b64 %0, {%1, %2};" : "=l"(r) : "f"(lo), "f"(hi)); return r;
}
__device__ __forceinline__ u64 bcast2(float v) {
    u64 r; asm("mov.b64 %0, {%1, %1};" : "=l"(r) : "f"(v)); return r;
}
__device__ __forceinline__ void upk2(u64 v, float& lo, float& hi) {
    asm("mov.b64 {%0, %1}, %2;" : "=f"(lo), "=f"(hi) : "l"(v));
}
__device__ __forceinline__ float ex2f(float x) {
    float r; asm("ex2.approx.ftz.f32 %0, %1;" : "=f"(r) : "f"(x)); return r;
}
__device__ __forceinline__ float rcpf(float x) {
    float r; asm("rcp.approx.ftz.f32 %0, %1;" : "=f"(r) : "f"(x)); return r;
}
// d = (c >= 0) ? a : b
__device__ __forceinline__ float slctf(float a, float b, float c) {
    float d; asm("slct.f32.f32 %0, %1, %2, %3;" : "=f"(d) : "f"(a), "f"(b), "f"(c)); return d;
}

// Loop-invariant packed constants
struct PkConsts {
    u64 nl2e, one, two, neg1;
    u64 c6, c5, c4, c3, c2, c1, c0;
    u64 quarter, sg, sp, magic;
};
__device__ __forceinline__ PkConsts make_consts() {
    PkConsts K;
    K.nl2e = bcast2(-1.4426950408889634f);   // -log2(e)
    K.one  = bcast2(1.0f);
    K.two  = bcast2(2.0f);
    K.neg1 = bcast2(-1.0f);
    // log1p(e) = ln(3/2) + ln(1 + u/3), u = 2e-1, Taylor deg 6
    K.c6 = bcast2(-2.2862368e-4f);
    K.c5 = bcast2( 8.2304527e-4f);
    K.c4 = bcast2(-3.0864198e-3f);
    K.c3 = bcast2( 1.2345679e-2f);
    K.c2 = bcast2(-5.5555556e-2f);
    K.c1 = bcast2( 3.3333333e-1f);
    K.c0 = bcast2( 4.0546511e-1f);
    K.quarter = bcast2(0.25f);
    K.sg = bcast2(SCALE_G);
    K.sp = bcast2(SCALE_P);
    K.magic = bcast2(MAGICF);
    return K;
}

// ---------------------------------------------------------------------------
// Zero accumulators
// ---------------------------------------------------------------------------
__global__ void zero_kernel() {
    int i = blockIdx.x * blockDim.x + threadIdx.x;
    if (i < PQ * NB) { d_G[i] = 0.f; d_Pb[i] = 0.f; }
    if (i < PQ) d_Sel[i] = 0.f;
    if (i < NB) d_cnt[i] = 0;
}

// ---------------------------------------------------------------------------
// Prep: labels int32 -> uint8, histogram counts
// ---------------------------------------------------------------------------
__global__ void prep_kernel(const int* __restrict__ labels) {
    __shared__ int h[NB];
    if (threadIdx.x < NB) h[threadIdx.x] = 0;
    __syncthreads();

    int i = blockIdx.x * blockDim.x + threadIdx.x;   // index in groups of 4
    if (i < PP / 4) {
        int4 l4 = reinterpret_cast<const int4*>(labels)[i];
        uchar4 u;
        u.x = (unsigned char)l4.x; u.y = (unsigned char)l4.y;
        u.z = (unsigned char)l4.z; u.w = (unsigned char)l4.w;
        reinterpret_cast<uchar4*>(d_lab8)[i] = u;
        atomicAdd(&h[l4.x], 1);
        atomicAdd(&h[l4.y], 1);
        atomicAdd(&h[l4.z], 1);
        atomicAdd(&h[l4.w], 1);
    }
    __syncthreads();
    if (threadIdx.x < NB && h[threadIdx.x] != 0)
        atomicAdd(&d_cnt[threadIdx.x], h[threadIdx.x]);
}

// ---------------------------------------------------------------------------
// Packed pair processing: two elements per f32x2 pipeline.
//   e  = exp(-|x|), s = 1/(1+e), L = log1p(e) (poly), os = e*s
//   A  = os^2 * L,  B = s^2 * (|x| + L)
//   sel = (x<0 ? A : B);  p = (x<0 ? os : s)
//   g = 0.25*(A+B) - sel;  {g,p} fixed-point packed -> one u64 smem atomic
//   nselacc accumulates -sel (packed).
// ---------------------------------------------------------------------------
__device__ __forceinline__ void pair_process(u64 X, int lab0, int lab1,
                                             u64* __restrict__ bin,
                                             const PkConsts& K, u64& nselacc) {
    u64 AX = X & 0x7FFFFFFF7FFFFFFFull;      // |x| both halves (2x LOP3 imm)
    u64 T;  MUL2(T, AX, K.nl2e);             // -|x| * log2(e)
    float t0, t1; upk2(T, t0, t1);
    u64 E = pk2(ex2f(t0), ex2f(t1));         // e = exp(-|x|)
    u64 EP1; ADD2(EP1, E, K.one);
    float q0, q1; upk2(EP1, q0, q1);
    u64 S = pk2(rcpf(q0), rcpf(q1));         // s = 1/(1+e) = sigmoid(|x|)

    u64 U; FMA2(U, E, K.two, K.neg1);        // u = 2e - 1
    u64 L;
    FMA2(L, U, K.c6, K.c5);
    FMA2(L, L, U, K.c4);
    FMA2(L, L, U, K.c3);
    FMA2(L, L, U, K.c2);
    FMA2(L, L, U, K.c1);
    FMA2(L, L, U, K.c0);                     // L = log1p(e)

    u64 OS;  MUL2(OS, E, S);                 // sigmoid(-|x|)
    u64 AXL; ADD2(AXL, AX, L);
    u64 OS2; MUL2(OS2, OS, OS);
    u64 Apk; MUL2(Apk, OS2, L);              // A = os^2 * L
    u64 S2;  MUL2(S2, S, S);
    u64 Bpk; MUL2(Bpk, S2, AXL);             // B = s^2 * (|x|+L)
    u64 ABpk; ADD2(ABpk, Apk, Bpk);

    u64 NA = Apk ^ 0x8000000080000000ull;    // -A, -B (ALU)
    u64 NBp = Bpk ^ 0x8000000080000000ull;
    float na0, na1, nb0, nb1, x0, x1, os0, os1, s0, s1;
    upk2(NA, na0, na1); upk2(NBp, nb0, nb1);
    upk2(X, x0, x1); upk2(OS, os0, os1); upk2(S, s0, s1);

    // nsel = -(x<0 ? A : B); pp = (x<0 ? os : s)
    u64 NSEL = pk2(slctf(nb0, na0, x0), slctf(nb1, na1, x1));
    u64 PPk  = pk2(slctf(s0, os0, x0),  slctf(s1, os1, x1));

    u64 G;  FMA2(G, ABpk, K.quarter, NSEL);  // g = 0.25(A+B) - sel
    u64 GF; FMA2(GF, G, K.sg, K.magic);      // magic-number fixed point
    u64 PF; FMA2(PF, PPk, K.sp, K.magic);
    ADD2(nselacc, nselacc, NSEL);

    float gf0, gf1, pf0, pf1;
    upk2(GF, gf0, gf1); upk2(PF, pf0, pf1);
    unsigned int gi0 = __float_as_uint(gf0) - MAGIC_I;
    unsigned int gi1 = __float_as_uint(gf1) - MAGIC_I;
    unsigned int pi0 = __float_as_uint(pf0) - MAGIC_I;
    unsigned int pi1 = __float_as_uint(pf1) - MAGIC_I;

    atomicAdd(bin + lab0, ((u64)gi0 << 32) | (u64)pi0);
    atomicAdd(bin + lab1, ((u64)gi1 << 32) | (u64)pi1);
}

__global__ __launch_bounds__(256) void cost_kernel(const float* __restrict__ pm) {
    __shared__ u64 bins[NREP][NB + 4];
    int tid = threadIdx.x;
    for (int i = tid; i < NREP * (NB + 4); i += 256)
        (&bins[0][0])[i] = 0ull;
    __syncthreads();

    int q     = blockIdx.x;
    int chunk = blockIdx.y;

    const int nf4    = PP / 4;               // 50000 float4 per row
    const int f4_per = nf4 / NCHUNK;         // 6250
    int s4 = chunk * f4_per;
    int e4 = s4 + f4_per;

    const float4* xv = reinterpret_cast<const float4*>(pm + (size_t)q * PP);
    const uchar4* lv = reinterpret_cast<const uchar4*>(d_lab8);

    u64* bin = &bins[tid & (NREP - 1)][0];
    const PkConsts K = make_consts();

    u64 nselacc = 0ull;   // bit pattern of (0.f, 0.f)
    for (int i4 = s4 + tid; i4 < e4; i4 += 256) {
        ulonglong2 xx = __ldcs(reinterpret_cast<const ulonglong2*>(xv + i4));
        uchar4 lb = lv[i4];
        pair_process(xx.x, lb.x, lb.y, bin, K, nselacc);
        pair_process(xx.y, lb.z, lb.w, bin, K, nselacc);
    }
    __syncthreads();

    if (tid < NB) {
        u64 v = 0ull;
        #pragma unroll
        for (int r = 0; r < NREP; r++) v += bins[r][tid];
        int gi = (int)(v >> 32);                 // lo bounded => no carry into hi
        unsigned int pi = (unsigned int)(v & 0xFFFFFFFFull);
        atomicAdd(&d_G[q * NB + tid],  (float)gi * INV_SCALE_G);
        atomicAdd(&d_Pb[q * NB + tid], (float)pi * INV_SCALE_P);
    }
    // selacc = -(nsel lo + nsel hi); warp-reduce, one global atomic per warp
    float nlo, nhi; upk2(nselacc, nlo, nhi);
    float selacc = -(nlo + nhi);
    #pragma unroll
    for (int o = 16; o; o >>= 1)
        selacc += __shfl_xor_sync(0xFFFFFFFFu, selacc, o);
    if ((tid & 31) == 0)
        atomicAdd(&d_Sel[q], selacc);
}

// ---------------------------------------------------------------------------
// Finalize: out[q,j] = cost_mask + cost_dice
// ---------------------------------------------------------------------------
__global__ void finalize_kernel(float* __restrict__ out) {
    int q = blockIdx.x, tid = threadIdx.x;
    __shared__ float red[4];

    float pv = (tid < NB) ? d_Pb[q * NB + tid] : 0.f;
    float w = pv;
    #pragma unroll
    for (int o = 16; o; o >>= 1)
        w += __shfl_xor_sync(0xFFFFFFFFu, w, o);
    if ((tid & 31) == 0) red[tid >> 5] = w;
    __syncthreads();
    float Psum = red[0] + red[1] + red[2] + red[3];

    if (tid < NB) {
        float cm  = (d_G[q * NB + tid] + 0.75f * d_Sel[q]) * (1.0f / (float)PP);
        float num = fmaf(2.0f, pv, 1.0f);
        float den = Psum + (float)d_cnt[tid] + 1.0f;
        out[q * NB + tid] = cm + 1.0f - num / den;
    }
}

// ---------------------------------------------------------------------------
extern "C" void kernel_launch(void* const* d_in, const int* in_sizes, int n_in,
                              void* d_out, int out_size) {
    const float* pm     = (const float*)d_in[0];
    const int*   labels = (const int*)d_in[1];
    (void)in_sizes; (void)n_in; (void)out_size;

    zero_kernel<<<160, 256>>>();
    prep_kernel<<<(PP / 4 + 255) / 256, 256>>>(labels);
    cost_kernel<<<dim3(PQ, NCHUNK), 256>>>(pm);
    finalize_kernel<<<PQ, 128>>>((float*)d_out);
}